// round 3
// baseline (speedup 1.0000x reference)
#include <cuda_runtime.h>
#include <cstddef>

#define NPART 65536
#define NEDGE 524288
#define RIG   4096
#define NF    128
#define ST    36          // transposed-activation row stride (floats); 36*4=144B, 16B-aligned, 4-way store conflicts only

typedef unsigned long long ull;

// ---------------- device scratch ----------------
__device__ float g_mean[8];
__device__ float g_pbase[(size_t)NPART * NF];
__device__ float g_base[(size_t)NEDGE * NF];
__device__ float g_A[(size_t)NPART * NF];
__device__ float g_B[(size_t)NPART * NF];
__device__ float g_agg[(size_t)NPART * NF];
__device__ float g_effect[(size_t)NPART * NF];
__device__ float g_vec[NF];
__device__ float g_rigid[16];

// ---------------- f32x2 helpers ----------------
__device__ __forceinline__ ull pack2(float x, float y) {
    ull r; asm("mov.b64 %0, {%1, %2};" : "=l"(r) : "f"(x), "f"(y)); return r;
}
__device__ __forceinline__ void unpack2(ull v, float& x, float& y) {
    asm("mov.b64 {%0, %1}, %2;" : "=f"(x), "=f"(y) : "l"(v));
}
__device__ __forceinline__ void fma2(ull& d, ull a, ull b) {
    asm("fma.rn.f32x2 %0, %1, %2, %0;" : "+l"(d) : "l"(a), "l"(b));
}

// ---------------- building blocks ----------------
// Stage weight block: s_w[k*128 + o] = W[o*rs + off + k], k in [0,128). Conflict-free stores.
__device__ __forceinline__ void stage_w(const float* __restrict__ W, int rs, int off,
                                        float* __restrict__ sw, int o)
{
#pragma unroll
    for (int c = 0; c < 128; c += 4) {
        float4 v = __ldg(reinterpret_cast<const float4*>(W + o * rs + off + c));
        sw[(c + 0) * 128 + o] = v.x;
        sw[(c + 1) * 128 + o] = v.y;
        sw[(c + 2) * 128 + o] = v.z;
        sw[(c + 3) * 128 + o] = v.w;
    }
}

// Accumulate 32 rows for output channel o: acc[i] holds rows (2i, 2i+1).
// sin is transposed [128][ST]; sw is [k][128].
__device__ __forceinline__ void dotT_accum(const float* __restrict__ sw,
                                           const float* __restrict__ sin,
                                           ull acc[16], int o)
{
#pragma unroll 4
    for (int k = 0; k < 128; k++) {
        float wv = sw[k * 128 + o];
        ull wk = pack2(wv, wv);
        const float4* a4 = reinterpret_cast<const float4*>(sin + k * ST);
#pragma unroll
        for (int t = 0; t < 8; t++) {
            float4 v = a4[t];
            ull lo = pack2(v.x, v.y);
            ull hi = pack2(v.z, v.w);
            fma2(acc[2 * t + 0], wk, lo);
            fma2(acc[2 * t + 1], wk, hi);
        }
    }
}

// Small-K (fully unrolled, weights in regs) variant.
template<int K>
__device__ __forceinline__ void dot_smallK(const float* __restrict__ wreg, float bias,
                                           const float* __restrict__ sin, ull acc[16])
{
    ull b2 = pack2(bias, bias);
#pragma unroll
    for (int i = 0; i < 16; i++) acc[i] = b2;
#pragma unroll
    for (int k = 0; k < K; k++) {
        ull wk = pack2(wreg[k], wreg[k]);
        const float4* a4 = reinterpret_cast<const float4*>(sin + k * ST);
#pragma unroll
        for (int t = 0; t < 8; t++) {
            float4 v = a4[t];
            ull lo = pack2(v.x, v.y);
            ull hi = pack2(v.z, v.w);
            fma2(acc[2 * t + 0], wk, lo);
            fma2(acc[2 * t + 1], wk, hi);
        }
    }
}

__device__ __forceinline__ void init_acc(ull acc[16], float bias) {
    ull b2 = pack2(bias, bias);
#pragma unroll
    for (int i = 0; i < 16; i++) acc[i] = b2;
}

template<bool RELU>
__device__ __forceinline__ void store_sT(float* __restrict__ sout, ull acc[16], int o)
{
#pragma unroll
    for (int i = 0; i < 16; i++) {
        float x, y; unpack2(acc[i], x, y);
        if (RELU) { x = fmaxf(x, 0.f); y = fmaxf(y, 0.f); }
        *reinterpret_cast<float2*>(sout + o * ST + 2 * i) = make_float2(x, y);
    }
}

template<bool RELU>
__device__ __forceinline__ void store_g(float* __restrict__ g, int n0, ull acc[16], int o)
{
#pragma unroll
    for (int i = 0; i < 16; i++) {
        float x, y; unpack2(acc[i], x, y);
        if (RELU) { x = fmaxf(x, 0.f); y = fmaxf(y, 0.f); }
        g[(size_t)(n0 + 2 * i + 0) * 128 + o] = x;
        g[(size_t)(n0 + 2 * i + 1) * 128 + o] = y;
    }
}

// ---------------- kernels ----------------
__global__ void k_mean(const float* __restrict__ state)
{
    __shared__ float s[6];
    if (threadIdx.x < 6) s[threadIdx.x] = 0.f;
    __syncthreads();
    float loc[6] = {0, 0, 0, 0, 0, 0};
    for (int r = threadIdx.x; r < RIG; r += blockDim.x) {
#pragma unroll
        for (int d = 0; d < 6; d++) loc[d] += state[r * 6 + d];
    }
#pragma unroll
    for (int d = 0; d < 6; d++) atomicAdd(&s[d], loc[d]);
    __syncthreads();
    if (threadIdx.x < 6) g_mean[threadIdx.x] = s[threadIdx.x] * (1.f / RIG);
}

// particle encoder (15->128->128) fused with pbase = pp_w[:, :128] @ pe + pp_b
// dyn smem: sw 16384 | sa 128*ST | sb 128*ST | sin 15*ST(pad 544)
__global__ void __launch_bounds__(128)
k_pe(const float* __restrict__ state, const float* __restrict__ attr,
     const float* __restrict__ pe_w0, const float* __restrict__ pe_b0,
     const float* __restrict__ pe_w1, const float* __restrict__ pe_b1,
     const float* __restrict__ pp_w, const float* __restrict__ pp_b)
{
    extern __shared__ float sm[];
    float* sw  = sm;
    float* sa  = sm + 16384;
    float* sb  = sa + 128 * ST;
    float* sin = sb + 128 * ST;
    int o = threadIdx.x;
    int n0 = blockIdx.x * 32;

    // gather (transposed: sin[c][r]) + stage pe_w1
    for (int idx = o; idx < 32 * 15; idx += 128) {
        int r = idx / 15, c = idx % 15;
        int n = n0 + r;
        float v;
        if (c < 3)       v = attr[n * 3 + c];
        else if (c < 9)  { int d = c - 3; v = (n < RIG) ? state[n * 6 + d] - g_mean[d] : 0.f; }
        else             v = state[n * 6 + (c - 9)];
        sin[c * ST + r] = v;
    }
    stage_w(pe_w1, 128, 0, sw, o);
    __syncthreads();

    ull acc[16];
    // L0: 15 -> 128 (relu), weights in regs
    {
        float w[15];
#pragma unroll
        for (int k = 0; k < 15; k++) w[k] = __ldg(&pe_w0[o * 15 + k]);
        dot_smallK<15>(w, pe_b0[o], sin, acc);
        store_sT<true>(sa, acc, o);
    }
    __syncthreads();
    // L1: 128 -> 128 (relu)
    init_acc(acc, pe_b1[o]);
    dotT_accum(sw, sa, acc, o);
    store_sT<true>(sb, acc, o);
    __syncthreads();
    stage_w(pp_w, 256, 0, sw, o);
    __syncthreads();
    // pbase (no relu)
    init_acc(acc, pp_b[o]);
    dotT_accum(sw, sb, acc, o);
    store_g<false>(g_pbase, n0, acc, o);
}

// relation encoder (31->128->128->128) fused with base = rp_w[:, :128] @ relenc + rp_b
// dyn smem: sw 16384 | sa 128*ST | sb 128*ST | sin 31*ST(pad 1152)
__global__ void __launch_bounds__(128)
k_edge(const float* __restrict__ attr, const float* __restrict__ state,
       const float* __restrict__ Ra,
       const int* __restrict__ recv, const int* __restrict__ send,
       const float* __restrict__ re_w0, const float* __restrict__ re_b0,
       const float* __restrict__ re_w1, const float* __restrict__ re_b1,
       const float* __restrict__ re_w2, const float* __restrict__ re_b2,
       const float* __restrict__ rp_w, const float* __restrict__ rp_b)
{
    extern __shared__ float sm[];
    float* sw  = sm;
    float* sa  = sm + 16384;
    float* sb  = sa + 128 * ST;
    float* sin = sb + 128 * ST;
    int o = threadIdx.x;
    int e0 = blockIdx.x * 32;

    for (int idx = o; idx < 32 * 31; idx += 128) {
        int r = idx / 31, c = idx % 31;
        int e = e0 + r;
        float v;
        if (c < 3)       { v = attr[recv[e] * 3 + c]; }
        else if (c < 9)  { int n = recv[e]; int d = c - 3;
                           v = (n < RIG) ? state[n * 6 + d] - g_mean[d] : 0.f; }
        else if (c < 12) { v = attr[send[e] * 3 + (c - 9)]; }
        else if (c < 18) { int n = send[e]; int d = c - 12;
                           v = (n < RIG) ? state[n * 6 + d] - g_mean[d] : 0.f; }
        else if (c < 24) { v = state[recv[e] * 6 + (c - 18)]; }
        else if (c < 30) { v = state[send[e] * 6 + (c - 24)]; }
        else             { v = Ra[e]; }
        sin[c * ST + r] = v;
    }
    stage_w(re_w1, 128, 0, sw, o);
    __syncthreads();

    ull acc[16];
    // L0: 31 -> 128 (relu)
    {
        float w[31];
#pragma unroll
        for (int k = 0; k < 31; k++) w[k] = __ldg(&re_w0[o * 31 + k]);
        dot_smallK<31>(w, re_b0[o], sin, acc);
        store_sT<true>(sa, acc, o);
    }
    __syncthreads();
    // L1
    init_acc(acc, re_b1[o]);
    dotT_accum(sw, sa, acc, o);
    store_sT<true>(sb, acc, o);
    __syncthreads();
    stage_w(re_w2, 128, 0, sw, o);
    __syncthreads();
    // L2
    init_acc(acc, re_b2[o]);
    dotT_accum(sw, sb, acc, o);
    store_sT<true>(sa, acc, o);
    __syncthreads();
    stage_w(rp_w, 384, 0, sw, o);
    __syncthreads();
    // base = rp_w[:, :128] @ relenc + rp_b  (pre-relu)
    init_acc(acc, rp_b[o]);
    dotT_accum(sw, sa, acc, o);
    store_g<false>(g_base, e0, acc, o);
}

// A = rp_w[:,128:256] @ effect ; B = rp_w[:,256:384] @ effect
// dyn smem: sw 16384 | sa 128*ST
__global__ void __launch_bounds__(128)
k_prop_node(const float* __restrict__ rp_w)
{
    extern __shared__ float sm[];
    float* sw = sm;
    float* sa = sm + 16384;
    int o = threadIdx.x;
    int n0 = blockIdx.x * 32;

    // transpose-load effect tile: sa[o][r]
#pragma unroll 4
    for (int r = 0; r < 32; r++) sa[o * ST + r] = g_effect[(size_t)(n0 + r) * 128 + o];
    stage_w(rp_w, 384, 128, sw, o);
    __syncthreads();

    ull acc[16];
    init_acc(acc, 0.f);
    dotT_accum(sw, sa, acc, o);
    store_g<false>(g_A, n0, acc, o);
    __syncthreads();
    stage_w(rp_w, 384, 256, sw, o);
    __syncthreads();
    init_acc(acc, 0.f);
    dotT_accum(sw, sa, acc, o);
    store_g<false>(g_B, n0, acc, o);
}

// per-edge: val = relu(base [+ A[recv] + B[send]]); agg[recv] += val
template<bool FIRST>
__global__ void k_prop_edge(const int* __restrict__ recv, const int* __restrict__ send)
{
    int gid = blockIdx.x * 256 + threadIdx.x;
    int e = gid >> 5;
    int q = gid & 31;
    int rv = recv[e];
    float4 b4 = *reinterpret_cast<const float4*>(&g_base[(size_t)e * 128 + q * 4]);
    float x = b4.x, y = b4.y, z = b4.z, w = b4.w;
    if (!FIRST) {
        int sd = send[e];
        float4 a4 = *reinterpret_cast<const float4*>(&g_A[(size_t)rv * 128 + q * 4]);
        float4 c4 = *reinterpret_cast<const float4*>(&g_B[(size_t)sd * 128 + q * 4]);
        x += a4.x + c4.x; y += a4.y + c4.y; z += a4.z + c4.z; w += a4.w + c4.w;
    }
    x = fmaxf(x, 0.f); y = fmaxf(y, 0.f); z = fmaxf(z, 0.f); w = fmaxf(w, 0.f);
    float* dst = &g_agg[(size_t)rv * 128 + q * 4];
    atomicAdd(dst + 0, x);
    atomicAdd(dst + 1, y);
    atomicAdd(dst + 2, z);
    atomicAdd(dst + 3, w);
}

// effect = relu(pbase + pp_w[:,128:256] @ agg)
// dyn smem: sw 16384 | sa 128*ST
__global__ void __launch_bounds__(128)
k_effect(const float* __restrict__ pp_w)
{
    extern __shared__ float sm[];
    float* sw = sm;
    float* sa = sm + 16384;
    int o = threadIdx.x;
    int n0 = blockIdx.x * 32;

#pragma unroll 4
    for (int r = 0; r < 32; r++) sa[o * ST + r] = g_agg[(size_t)(n0 + r) * 128 + o];
    stage_w(pp_w, 256, 128, sw, o);
    __syncthreads();

    ull acc[16];
#pragma unroll
    for (int i = 0; i < 16; i++)
        acc[i] = pack2(g_pbase[(size_t)(n0 + 2 * i) * 128 + o],
                       g_pbase[(size_t)(n0 + 2 * i + 1) * 128 + o]);
    dotT_accum(sw, sa, acc, o);
    store_g<true>(g_effect, n0, acc, o);
}

__global__ void k_pool()
{
    int o = threadIdx.x;
    int r0 = blockIdx.x * 256;
    float s = 0.f;
    for (int r = 0; r < 256; r++) s += g_effect[(size_t)(r0 + r) * 128 + o];
    atomicAdd(&g_vec[o], s);
}

__global__ void k_rigid(const float* __restrict__ rg_w0, const float* __restrict__ rg_b0,
                        const float* __restrict__ rg_w1, const float* __restrict__ rg_b1,
                        const float* __restrict__ rg_w2, const float* __restrict__ rg_b2)
{
    __shared__ float p[128], h[128], t7[8];
    int o = threadIdx.x;
    p[o] = g_vec[o] * (1.f / RIG);
    __syncthreads();
    {
        float acc = rg_b0[o];
        for (int k = 0; k < 128; k++) acc = fmaf(rg_w0[o * 128 + k], p[k], acc);
        h[o] = fmaxf(acc, 0.f);
    }
    __syncthreads();
    {
        float acc = rg_b1[o];
        for (int k = 0; k < 128; k++) acc = fmaf(rg_w1[o * 128 + k], h[k], acc);
        p[o] = fmaxf(acc, 0.f);
    }
    __syncthreads();
    if (o < 7) {
        float acc = rg_b2[o];
        for (int k = 0; k < 128; k++) acc = fmaf(rg_w2[o * 128 + k], p[k], acc);
        t7[o] = acc;
    }
    __syncthreads();
    if (o == 0) {
        float t0 = t7[0], t1 = t7[1], t2 = t7[2], t3 = t7[3];
        float inv = rsqrtf(t0 * t0 + t1 * t1 + t2 * t2 + t3 * t3);
        float w = t0 * inv, x = t1 * inv, y = t2 * inv, z = t3 * inv;
        g_rigid[0] = 1.f - 2.f * (y * y + z * z);
        g_rigid[1] = 2.f * (x * y + z * w);
        g_rigid[2] = 2.f * (x * z - y * w);
        g_rigid[3] = 2.f * (x * y - z * w);
        g_rigid[4] = 1.f - 2.f * (x * x + z * z);
        g_rigid[5] = 2.f * (y * z + x * w);
        g_rigid[6] = 2.f * (x * z + y * w);
        g_rigid[7] = 2.f * (y * z - x * w);
        g_rigid[8] = 1.f - 2.f * (x * x + y * y);
        g_rigid[9]  = t7[4]; g_rigid[10] = t7[5]; g_rigid[11] = t7[6];
        g_rigid[12] = g_mean[0]; g_rigid[13] = g_mean[1]; g_rigid[14] = g_mean[2];
    }
}

__global__ void k_out_rigid(const float* __restrict__ state, float* __restrict__ out)
{
    int i = blockIdx.x * 256 + threadIdx.x;
    float R0 = g_rigid[0], R1 = g_rigid[1], R2 = g_rigid[2];
    float R3 = g_rigid[3], R4 = g_rigid[4], R5 = g_rigid[5];
    float R6 = g_rigid[6], R7 = g_rigid[7], R8 = g_rigid[8];
    float bx = g_rigid[9], by = g_rigid[10], bz = g_rigid[11];
    float cx = g_rigid[12], cy = g_rigid[13], cz = g_rigid[14];
    float p0x = state[i * 6 + 0], p0y = state[i * 6 + 1], p0z = state[i * 6 + 2];
    float dx = p0x - cx, dy = p0y - cy, dz = p0z - cz;
    float p1x = dx * R0 + dy * R3 + dz * R6 + bx + cx;
    float p1y = dx * R1 + dy * R4 + dz * R7 + by + cy;
    float p1z = dx * R2 + dy * R5 + dz * R8 + bz + cz;
    out[i * 3 + 0] = (p1x - p0x) * 60.f;
    out[i * 3 + 1] = (p1y - p0y) * 60.f;
    out[i * 3 + 2] = (p1z - p0z) * 60.f;
}

// fluid head: 2x (128->128 relu) + 128->3
// dyn smem: sw 16384 | sa 128*ST | sb 128*ST
__global__ void __launch_bounds__(128)
k_fluid(const float* __restrict__ fl_w0, const float* __restrict__ fl_b0,
        const float* __restrict__ fl_w1, const float* __restrict__ fl_b1,
        const float* __restrict__ fl_w2, const float* __restrict__ fl_b2,
        float* __restrict__ out)
{
    extern __shared__ float sm[];
    float* sw = sm;
    float* sa = sm + 16384;
    float* sb = sa + 128 * ST;
    int o = threadIdx.x;
    int n0 = RIG + blockIdx.x * 32;

#pragma unroll 4
    for (int r = 0; r < 32; r++) sa[o * ST + r] = g_effect[(size_t)(n0 + r) * 128 + o];
    stage_w(fl_w0, 128, 0, sw, o);
    __syncthreads();

    ull acc[16];
    init_acc(acc, fl_b0[o]);
    dotT_accum(sw, sa, acc, o);
    store_sT<true>(sb, acc, o);
    __syncthreads();
    stage_w(fl_w1, 128, 0, sw, o);
    __syncthreads();
    init_acc(acc, fl_b1[o]);
    dotT_accum(sw, sb, acc, o);
    store_sT<true>(sa, acc, o);
    __syncthreads();

    if (o < 96) {
        int r = o / 3, j = o % 3;
        float acc1 = fl_b2[j];
        for (int k = 0; k < 128; k++)
            acc1 = fmaf(__ldg(&fl_w2[j * 128 + k]), sa[k * ST + r], acc1);
        out[(size_t)(n0 + r) * 3 + j] = acc1;
    }
}

// ---------------- launch ----------------
extern "C" void kernel_launch(void* const* d_in, const int* in_sizes, int n_in,
                              void* d_out, int out_size)
{
    const float* state  = (const float*)d_in[0];
    const float* attr   = (const float*)d_in[1];
    const float* Ra     = (const float*)d_in[2];
    const int*   recv   = (const int*)d_in[3];
    const int*   send   = (const int*)d_in[4];
    const float* pe_w0  = (const float*)d_in[5];
    const float* pe_b0  = (const float*)d_in[6];
    const float* pe_w1  = (const float*)d_in[7];
    const float* pe_b1  = (const float*)d_in[8];
    const float* re_w0  = (const float*)d_in[9];
    const float* re_b0  = (const float*)d_in[10];
    const float* re_w1  = (const float*)d_in[11];
    const float* re_b1  = (const float*)d_in[12];
    const float* re_w2  = (const float*)d_in[13];
    const float* re_b2  = (const float*)d_in[14];
    const float* rp_w   = (const float*)d_in[15];
    const float* rp_b   = (const float*)d_in[16];
    const float* pp_w   = (const float*)d_in[17];
    const float* pp_b   = (const float*)d_in[18];
    const float* rg_w0  = (const float*)d_in[19];
    const float* rg_b0  = (const float*)d_in[20];
    const float* rg_w1  = (const float*)d_in[21];
    const float* rg_b1  = (const float*)d_in[22];
    const float* rg_w2  = (const float*)d_in[23];
    const float* rg_b2  = (const float*)d_in[24];
    const float* fl_w0  = (const float*)d_in[25];
    const float* fl_b0  = (const float*)d_in[26];
    const float* fl_w1  = (const float*)d_in[27];
    const float* fl_b1  = (const float*)d_in[28];
    const float* fl_w2  = (const float*)d_in[29];
    const float* fl_b2  = (const float*)d_in[30];
    float* out = (float*)d_out;

    // dynamic smem sizes (bytes)
    const int SM_PE    = (16384 + 2 * 128 * ST + 15 * ST + 4) * 4;
    const int SM_EDGE  = (16384 + 2 * 128 * ST + 31 * ST + 4) * 4;
    const int SM_NODE  = (16384 + 128 * ST) * 4;
    const int SM_FLUID = (16384 + 2 * 128 * ST) * 4;

    cudaFuncSetAttribute(k_pe,        cudaFuncAttributeMaxDynamicSharedMemorySize, SM_PE);
    cudaFuncSetAttribute(k_edge,      cudaFuncAttributeMaxDynamicSharedMemorySize, SM_EDGE);
    cudaFuncSetAttribute(k_prop_node, cudaFuncAttributeMaxDynamicSharedMemorySize, SM_NODE);
    cudaFuncSetAttribute(k_effect,    cudaFuncAttributeMaxDynamicSharedMemorySize, SM_NODE);
    cudaFuncSetAttribute(k_fluid,     cudaFuncAttributeMaxDynamicSharedMemorySize, SM_FLUID);

    void* p_agg = nullptr; void* p_vec = nullptr;
    cudaGetSymbolAddress(&p_agg, g_agg);
    cudaGetSymbolAddress(&p_vec, g_vec);

    k_mean<<<1, 256>>>(state);
    k_pe<<<NPART / 32, 128, SM_PE>>>(state, attr, pe_w0, pe_b0, pe_w1, pe_b1, pp_w, pp_b);
    k_edge<<<NEDGE / 32, 128, SM_EDGE>>>(attr, state, Ra, recv, send,
                                         re_w0, re_b0, re_w1, re_b1, re_w2, re_b2, rp_w, rp_b);

    // propagation step 1 (effect == 0 -> rel_eff = relu(base))
    cudaMemsetAsync(p_agg, 0, (size_t)NPART * NF * sizeof(float));
    k_prop_edge<true><<<NEDGE * 32 / 256, 256>>>(recv, send);
    k_effect<<<NPART / 32, 128, SM_NODE>>>(pp_w);

    // propagation step 2
    k_prop_node<<<NPART / 32, 128, SM_NODE>>>(rp_w);
    cudaMemsetAsync(p_agg, 0, (size_t)NPART * NF * sizeof(float));
    k_prop_edge<false><<<NEDGE * 32 / 256, 256>>>(recv, send);
    k_effect<<<NPART / 32, 128, SM_NODE>>>(pp_w);

    // heads
    cudaMemsetAsync(p_vec, 0, NF * sizeof(float));
    k_pool<<<16, 128>>>();
    k_rigid<<<1, 128>>>(rg_w0, rg_b0, rg_w1, rg_b1, rg_w2, rg_b2);
    k_out_rigid<<<RIG / 256, 256>>>(state, out);
    k_fluid<<<(NPART - RIG) / 32, 128, SM_FLUID>>>(fl_w0, fl_b0, fl_w1, fl_b1, fl_w2, fl_b2, out);
}